// round 4
// baseline (speedup 1.0000x reference)
#include <cuda_runtime.h>

#define NTOK 32768
#define NH 32
#define NC 27  // float4 chunks per token: Q=0..8, K=9..17, V=18..26 (each section 34 padded to 36)

// Scratch: 10 obs slices (pred reuses slice 0). 141.6 MB
__device__ float4 g_scratch[10 * NC * NTOK];
// Folded fc_sa @ out_proj
__device__ float g_cw[34][32];
__device__ float g_cb[32];

typedef unsigned long long u64;

__device__ __forceinline__ u64 pack2(float lo, float hi) {
    u64 r; asm("mov.b64 %0, {%1, %2};" : "=l"(r) : "f"(lo), "f"(hi)); return r;
}
__device__ __forceinline__ void unpack2(u64 v, float& lo, float& hi) {
    asm("mov.b64 {%0, %1}, %2;" : "=f"(lo), "=f"(hi) : "l"(v));
}
__device__ __forceinline__ u64 ffma2(u64 a, u64 b, u64 c) {
    u64 d; asm("fma.rn.f32x2 %0, %1, %2, %3;" : "=l"(d) : "l"(a), "l"(b), "l"(c)); return d;
}
__device__ __forceinline__ u64 fadd2(u64 a, u64 b) {
    u64 d; asm("add.rn.f32x2 %0, %1, %2;" : "=l"(d) : "l"(a), "l"(b)); return d;
}

// ---------------------------------------------------------------------------
__global__ void __launch_bounds__(128) precomp_kernel(
    const float* __restrict__ saw, const float* __restrict__ opw,
    const float* __restrict__ opb, const float* __restrict__ sab)
{
    int tid = threadIdx.x;
    for (int idx = tid; idx < 34 * 32; idx += 128) {
        int j = idx / 32, k = idx % 32;
        float acc = 0.f;
#pragma unroll
        for (int i = 0; i < 34; i++) acc += saw[k * 34 + i] * opw[i * 34 + j];
        g_cw[j][k] = acc;
    }
    if (tid < 32) {
        float acc = sab[tid];
#pragma unroll
        for (int i = 0; i < 34; i++) acc += saw[tid * 34 + i] * opb[i];
        g_cb[tid] = acc;
    }
}

// ---------------------------------------------------------------------------
// QKV: 2 threads per token; half 0 -> chunks 0..13, half 1 -> chunks 14..26.
// ---------------------------------------------------------------------------
template<int NCK>
__device__ __forceinline__ void qkv_group(int c0, const float* __restrict__ f,
                                          const float4* sw, const float4* sb,
                                          float4* outp)
{
    u64 a[2 * NCK];
#pragma unroll
    for (int cc = 0; cc < NCK; cc++) {
        ulonglong2 bv = *reinterpret_cast<const ulonglong2*>(&sb[c0 + cc]);
        a[2 * cc] = bv.x; a[2 * cc + 1] = bv.y;
    }
#pragma unroll
    for (int i = 0; i < 36; i++) {
        u64 fp = pack2(f[i], f[i]);
#pragma unroll
        for (int cc = 0; cc < NCK; cc++) {
            ulonglong2 w = *reinterpret_cast<const ulonglong2*>(&sw[i * NC + c0 + cc]);
            a[2 * cc]     = ffma2(w.x, fp, a[2 * cc]);
            a[2 * cc + 1] = ffma2(w.y, fp, a[2 * cc + 1]);
        }
    }
#pragma unroll
    for (int cc = 0; cc < NCK; cc++) {
        ulonglong2 o; o.x = a[2 * cc]; o.y = a[2 * cc + 1];
        outp[(size_t)(c0 + cc) * NTOK] = *reinterpret_cast<float4*>(&o);
    }
}

__global__ void __launch_bounds__(128) qkv_kernel(
    const float* __restrict__ hbase,   // (z, NTOK, 32)
    const float* __restrict__ ipw,     // (102, 34)
    const float* __restrict__ ipb)     // (102)
{
    __shared__ __align__(16) float4 sw[36 * NC];  // sw[i*NC + c]
    __shared__ __align__(16) float4 sb[NC];

    int tid = threadIdx.x;
    for (int idx = tid; idx < 36 * NC; idx += 128) {
        int i = idx / NC, c = idx % NC;
        int sec = c / 9, ww = 4 * (c % 9);
        float4 v;
        v.x = (i < 34 && ww + 0 < 34) ? ipw[(sec * 34 + ww + 0) * 34 + i] : 0.f;
        v.y = (i < 34 && ww + 1 < 34) ? ipw[(sec * 34 + ww + 1) * 34 + i] : 0.f;
        v.z = (i < 34 && ww + 2 < 34) ? ipw[(sec * 34 + ww + 2) * 34 + i] : 0.f;
        v.w = (i < 34 && ww + 3 < 34) ? ipw[(sec * 34 + ww + 3) * 34 + i] : 0.f;
        sw[idx] = v;
    }
    if (tid < NC) {
        int sec = tid / 9, ww = 4 * (tid % 9);
        float4 v;
        v.x = (ww + 0 < 34) ? ipb[sec * 34 + ww + 0] : 0.f;
        v.y = (ww + 1 < 34) ? ipb[sec * 34 + ww + 1] : 0.f;
        v.z = (ww + 2 < 34) ? ipb[sec * 34 + ww + 2] : 0.f;
        v.w = (ww + 3 < 34) ? ipb[sec * 34 + ww + 3] : 0.f;
        sb[tid] = v;
    }
    __syncthreads();

    int gtid = blockIdx.x * 128 + tid;     // 0..65535
    int n = gtid >> 1, hf = gtid & 1;

    const float4* h4 = reinterpret_cast<const float4*>(
        hbase + ((size_t)blockIdx.z * NTOK + n) * NH);

    float f[36];
#pragma unroll
    for (int i = 0; i < 8; i++) {
        float4 v = h4[i];
        f[4 * i + 0] = v.x; f[4 * i + 1] = v.y;
        f[4 * i + 2] = v.z; f[4 * i + 3] = v.w;
    }
    int p = n & 4095;
    f[32] = (float)(p >> 6) * (1.f / 64.f);
    f[33] = (float)(p & 63) * (1.f / 64.f);
    f[34] = 0.f; f[35] = 0.f;

    float4* outp = g_scratch + (size_t)blockIdx.z * NC * NTOK + n;

    if (hf == 0) {
        qkv_group<7>(0, f, sw, sb, outp);
        qkv_group<7>(7, f, sw, sb, outp);
    } else {
        qkv_group<7>(14, f, sw, sb, outp);
        qkv_group<6>(21, f, sw, sb, outp);
    }
}

// ---------------------------------------------------------------------------
// Attention: 2 threads per token (warp-lane pair, combine via shfl_xor 1).
//   half 0: E-chunks 0..3 (+ masked chunk 4), half 1: E-chunks 4..8.
// ---------------------------------------------------------------------------
__global__ void __launch_bounds__(128) attn_kernel(
    const float* __restrict__ hbase,   // residual input (z, NTOK, 32)
    float* __restrict__ obase,         // output (z, NTOK, 32)
    const float* __restrict__ f2w, const float* __restrict__ f2b,
    const float* __restrict__ lng, const float* __restrict__ lnb)
{
    __shared__ __align__(16) float s_cw[34][32];
    __shared__ __align__(16) float s_f2[32][32];
    __shared__ __align__(16) float s_cb[32];
    __shared__ __align__(16) float s_f2b[32];
    __shared__ float s_g[32], s_bb[32];

    int tid = threadIdx.x;
    for (int idx = tid; idx < 34 * 32; idx += 128)
        s_cw[idx / 32][idx % 32] = g_cw[idx / 32][idx % 32];
    for (int idx = tid; idx < 32 * 32; idx += 128) {
        int i = idx / 32, k = idx % 32;
        s_f2[i][k] = f2w[k * 32 + i];
    }
    if (tid < 32) {
        s_cb[tid] = g_cb[tid]; s_f2b[tid] = f2b[tid];
        s_g[tid] = lng[tid];   s_bb[tid] = lnb[tid];
    }
    __syncthreads();

    int gtid = blockIdx.x * 128 + tid;
    int n = gtid >> 1, hf = gtid & 1;

    int p = n & 4095;
    int row = p >> 6, col = p & 63;
    int rs = row + (row == 0) - (row == 63);
    int cs = col + (col == 0) - (col == 63);
    int jb = (n >> 12) * 4096;

    const float4* S = g_scratch + (size_t)blockIdx.z * NC * NTOK;

    int jt[9];
#pragma unroll
    for (int s = 0; s < 9; s++) {
        int dr = s / 3 - 1, dc = s % 3 - 1;
        jt[s] = jb + (rs + dr) * 64 + (cs + dc);
    }

    int cbase = 4 * hf;   // first owned E-chunk

    // --- q (center token), masked 5th chunk on half 0 ---
    u64 q01[5], q23[5];
#pragma unroll
    for (int cc = 0; cc < 5; cc++) {
        ulonglong2 qv = *reinterpret_cast<const ulonglong2*>(
            &S[(size_t)(cbase + cc) * NTOK + jt[4]]);
        q01[cc] = qv.x; q23[cc] = qv.y;
    }
    if (hf == 0) { q01[4] = 0ull; q23[4] = 0ull; }

    // --- scores (partial dot over own chunks, combine via shfl) ---
    float sc[9];
#pragma unroll
    for (int s = 0; s < 9; s++) {
        const float4* kp = S + (size_t)(9 + cbase) * NTOK + jt[s];
        u64 a0 = 0ull, a1 = 0ull;
#pragma unroll
        for (int cc = 0; cc < 5; cc++) {
            ulonglong2 kv = *reinterpret_cast<const ulonglong2*>(&kp[(size_t)cc * NTOK]);
            a0 = ffma2(q01[cc], kv.x, a0);
            a1 = ffma2(q23[cc], kv.y, a1);
        }
        float x0, x1, x2, x3;
        unpack2(a0, x0, x1); unpack2(a1, x2, x3);
        float ps = (x0 + x1) + (x2 + x3);
        ps += __shfl_xor_sync(0xffffffffu, ps, 1);
        sc[s] = ps * 0.17149858514250882f;  // 1/sqrt(34)
    }

    // --- softmax over 9 (both threads identical) ---
    float m = sc[0];
#pragma unroll
    for (int s = 1; s < 9; s++) m = fmaxf(m, sc[s]);
    float sum = 0.f;
#pragma unroll
    for (int s = 0; s < 9; s++) { sc[s] = __expf(sc[s] - m); sum += sc[s]; }
    float rinv = 1.f / sum;

    // --- av over own chunks ---
    u64 av01[5], av23[5];
#pragma unroll
    for (int cc = 0; cc < 5; cc++) { av01[cc] = 0ull; av23[cc] = 0ull; }
#pragma unroll
    for (int s = 0; s < 9; s++) {
        float wv = sc[s] * rinv;
        u64 wvp = pack2(wv, wv);
        const float4* vp = S + (size_t)(18 + cbase) * NTOK + jt[s];
#pragma unroll
        for (int cc = 0; cc < 5; cc++) {
            ulonglong2 vv = *reinterpret_cast<const ulonglong2*>(&vp[(size_t)cc * NTOK]);
            av01[cc] = ffma2(wvp, vv.x, av01[cc]);
            av23[cc] = ffma2(wvp, vv.y, av23[cc]);
        }
    }
    float avl[20];
#pragma unroll
    for (int cc = 0; cc < 5; cc++) {
        unpack2(av01[cc], avl[4 * cc + 0], avl[4 * cc + 1]);
        unpack2(av23[cc], avl[4 * cc + 2], avl[4 * cc + 3]);
    }
    // half0 owns av floats 0..15 (avl[0..15]); half1 owns 16..33 (avl[0..17]).

    // --- z = h + CW @ av + cb, input-split over j, combine ---
    u64 z[16];
    if (hf == 0) {
#pragma unroll
        for (int k = 0; k < 16; k++) z[k] = *reinterpret_cast<const u64*>(&s_cb[2 * k]);
        const float4* h4 = reinterpret_cast<const float4*>(
            hbase + ((size_t)blockIdx.z * NTOK + n) * NH);
#pragma unroll
        for (int q4 = 0; q4 < 8; q4++) {
            ulonglong2 hv = *reinterpret_cast<const ulonglong2*>(&h4[q4]);
            z[2 * q4]     = fadd2(z[2 * q4], hv.x);
            z[2 * q4 + 1] = fadd2(z[2 * q4 + 1], hv.y);
        }
#pragma unroll
        for (int jj = 0; jj < 16; jj++) {
            u64 ap = pack2(avl[jj], avl[jj]);
#pragma unroll
            for (int k = 0; k < 16; k++)
                z[k] = ffma2(ap, *reinterpret_cast<const u64*>(&s_cw[jj][2 * k]), z[k]);
        }
    } else {
#pragma unroll
        for (int k = 0; k < 16; k++) z[k] = 0ull;
#pragma unroll
        for (int jj = 0; jj < 18; jj++) {
            u64 ap = pack2(avl[jj], avl[jj]);
#pragma unroll
            for (int k = 0; k < 16; k++)
                z[k] = ffma2(ap, *reinterpret_cast<const u64*>(&s_cw[16 + jj][2 * k]), z[k]);
        }
    }
#pragma unroll
    for (int k = 0; k < 16; k++) {
        u64 other = __shfl_xor_sync(0xffffffffu, z[k], 1);
        z[k] = fadd2(z[k], other);
    }

    // own 16 inputs for fc2
    float zloc[16];
#pragma unroll
    for (int t = 0; t < 8; t++)
        unpack2(z[8 * hf + t], zloc[2 * t], zloc[2 * t + 1]);

    // --- u = f2w @ z + f2b, input-split over i, combine ---
    u64 u[16];
    if (hf == 0) {
#pragma unroll
        for (int k = 0; k < 16; k++) u[k] = *reinterpret_cast<const u64*>(&s_f2b[2 * k]);
    } else {
#pragma unroll
        for (int k = 0; k < 16; k++) u[k] = 0ull;
    }
#pragma unroll
    for (int ii = 0; ii < 16; ii++) {
        int i = 16 * hf + ii;
        u64 ap = pack2(zloc[ii], zloc[ii]);
#pragma unroll
        for (int k = 0; k < 16; k++)
            u[k] = ffma2(ap, *reinterpret_cast<const u64*>(&s_f2[i][2 * k]), u[k]);
    }
#pragma unroll
    for (int k = 0; k < 16; k++) {
        u64 other = __shfl_xor_sync(0xffffffffu, u[k], 1);
        u[k] = fadd2(u[k], other);
    }
    float uf[32];
#pragma unroll
    for (int k = 0; k < 16; k++) unpack2(u[k], uf[2 * k], uf[2 * k + 1]);

    // --- layernorm (redundant on pair) ---
    float mean = 0.f;
#pragma unroll
    for (int k = 0; k < 32; k++) mean += uf[k];
    mean *= (1.f / 32.f);
    float var = 0.f;
#pragma unroll
    for (int k = 0; k < 32; k++) { float d = uf[k] - mean; var += d * d; }
    var *= (1.f / 32.f);
    float r = rsqrtf(var + 1e-5f);

    float4* o4 = reinterpret_cast<float4*>(
        obase + ((size_t)blockIdx.z * NTOK + n) * NH);
#pragma unroll
    for (int k4 = 0; k4 < 4; k4++) {
        int kk = 4 * hf + k4;
        float4 y;
        y.x = (uf[4 * kk + 0] - mean) * r * s_g[4 * kk + 0] + s_bb[4 * kk + 0];
        y.y = (uf[4 * kk + 1] - mean) * r * s_g[4 * kk + 1] + s_bb[4 * kk + 1];
        y.z = (uf[4 * kk + 2] - mean) * r * s_g[4 * kk + 2] + s_bb[4 * kk + 2];
        y.w = (uf[4 * kk + 3] - mean) * r * s_g[4 * kk + 3] + s_bb[4 * kk + 3];
        o4[kk] = y;
    }
}

// ---------------------------------------------------------------------------
extern "C" void kernel_launch(void* const* d_in, const int* in_sizes, int n_in,
                              void* d_out, int out_size)
{
    const float* x   = (const float*)d_in[0];   // (10, 32768, 32)
    const float* ipw = (const float*)d_in[1];
    const float* ipb = (const float*)d_in[2];
    const float* opw = (const float*)d_in[3];
    const float* opb = (const float*)d_in[4];
    const float* saw = (const float*)d_in[5];
    const float* sab = (const float*)d_in[6];
    const float* f2w = (const float*)d_in[7];
    const float* f2b = (const float*)d_in[8];
    const float* lng = (const float*)d_in[9];
    const float* lnb = (const float*)d_in[10];
    float* out = (float*)d_out;                 // (60, 32768, 32)

    const int NB = (2 * NTOK) / 128;            // 512 blocks (2 threads/token)

    precomp_kernel<<<1, 128>>>(saw, opw, opb, sab);

    // Observation phase: 10 independent steps, batched over grid.z
    dim3 gobs(NB, 1, 10);
    qkv_kernel<<<gobs, 128>>>(x, ipw, ipb);
    attn_kernel<<<gobs, 128>>>(x, out, f2w, f2b, lng, lnb);

    // Prediction phase: 50 sequential steps rolling on the last output
    dim3 g1(NB, 1, 1);
    for (int i = 0; i < 50; i++) {
        const float* hprev = out + (size_t)(9 + i) * NTOK * NH;
        float* onext       = out + (size_t)(10 + i) * NTOK * NH;
        qkv_kernel<<<g1, 128>>>(hprev, ipw, ipb);
        attn_kernel<<<g1, 128>>>(hprev, onext, f2w, f2b, lng, lnb);
    }
}

// round 5
// speedup vs baseline: 2.6229x; 2.6229x over previous
#include <cuda_runtime.h>

#define NTOK 32768
#define NH 32
#define NCH 9                 // float4 feature chunks per token (36 floats: 32 h + 2 label + 2 pad)
#define SLICE (NCH * NTOK)    // float4s per feature slice

// Feature slices: 0..9 = obs inputs, 10..19 = obs outputs, 20..21 = pred ping-pong. ~103MB
__device__ float4 g_ftr[22 * SLICE];

// Precomputed folded weights
__device__ float g_M[36 * 36];     // (Wq^T Wk)/sqrt(34), padded, [i][j]
__device__ float g_kb[36];         // (Wk^T bq)/sqrt(34)
__device__ float g_qb[36];         // (Wq^T bk)/sqrt(34)
__device__ float g_cc[1];          // (bq.bk)/sqrt(34)
__device__ float g_cv[36][32];     // CV[j][k] = sum_i (saw@opw)[k][i] * Wv[i][j]
__device__ float g_cb2[32];        // saw@opb + sab + (saw@opw)@bv
__device__ float g_f2h[32][32];    // [i][k] = f2w[k][i] - colmean_i
__device__ float g_bh[32];         // f2b - mean(f2b)

typedef unsigned long long u64;

__device__ __forceinline__ u64 pack2(float lo, float hi) {
    u64 r; asm("mov.b64 %0, {%1, %2};" : "=l"(r) : "f"(lo), "f"(hi)); return r;
}
__device__ __forceinline__ void unpack2(u64 v, float& lo, float& hi) {
    asm("mov.b64 {%0, %1}, %2;" : "=f"(lo), "=f"(hi) : "l"(v));
}
__device__ __forceinline__ u64 ffma2(u64 a, u64 b, u64 c) {
    u64 d; asm("fma.rn.f32x2 %0, %1, %2, %3;" : "=l"(d) : "l"(a), "l"(b), "l"(c)); return d;
}
__device__ __forceinline__ u64 fadd2(u64 a, u64 b) {
    u64 d; asm("add.rn.f32x2 %0, %1, %2;" : "=l"(d) : "l"(a), "l"(b)); return d;
}
__device__ __forceinline__ u64 fmul2(u64 a, u64 b) {
    u64 d; asm("mul.rn.f32x2 %0, %1, %2;" : "=l"(d) : "l"(a), "l"(b)); return d;
}

// ---------------------------------------------------------------------------
__global__ void __launch_bounds__(256) precomp_kernel(
    const float* __restrict__ ipw, const float* __restrict__ ipb,
    const float* __restrict__ opw, const float* __restrict__ opb,
    const float* __restrict__ saw, const float* __restrict__ sab,
    const float* __restrict__ f2w, const float* __restrict__ f2b)
{
    __shared__ float sCW[32][34];   // saw @ opw
    int tid = threadIdx.x;
    const float SC = 0.17149858514250882f;  // 1/sqrt(34)

    for (int idx = tid; idx < 36 * 36; idx += 256) {
        int i = idx / 36, j = idx % 36;
        float acc = 0.f;
        if (i < 34 && j < 34)
            for (int e = 0; e < 34; e++) acc += ipw[e * 34 + i] * ipw[(34 + e) * 34 + j];
        g_M[idx] = acc * SC;
    }
    for (int j = tid; j < 36; j += 256) {
        float a = 0.f, b = 0.f;
        if (j < 34)
            for (int e = 0; e < 34; e++) {
                a += ipb[e] * ipw[(34 + e) * 34 + j];
                b += ipw[e * 34 + j] * ipb[34 + e];
            }
        g_kb[j] = a * SC;
        g_qb[j] = b * SC;
    }
    if (tid == 0) {
        float c = 0.f;
        for (int e = 0; e < 34; e++) c += ipb[e] * ipb[34 + e];
        g_cc[0] = c * SC;
    }
    for (int idx = tid; idx < 32 * 34; idx += 256) {
        int k = idx / 34, i = idx % 34;
        float acc = 0.f;
        for (int t = 0; t < 34; t++) acc += saw[k * 34 + t] * opw[t * 34 + i];
        sCW[k][i] = acc;
    }
    __syncthreads();
    for (int idx = tid; idx < 36 * 32; idx += 256) {
        int j = idx / 32, k = idx % 32;
        float acc = 0.f;
        if (j < 34)
            for (int i = 0; i < 34; i++) acc += sCW[k][i] * ipw[(68 + i) * 34 + j];
        g_cv[j][k] = acc;
    }
    for (int k = tid; k < 32; k += 256) {
        float acc = sab[k];
        for (int t = 0; t < 34; t++) acc += saw[k * 34 + t] * opb[t];
        for (int i = 0; i < 34; i++) acc += sCW[k][i] * ipb[68 + i];
        g_cb2[k] = acc;
    }
    for (int idx = tid; idx < 32 * 32; idx += 256) {
        int i = idx / 32, k = idx % 32;
        float mu = 0.f;
        for (int kk = 0; kk < 32; kk++) mu += f2w[kk * 32 + i];
        g_f2h[i][k] = f2w[k * 32 + i] - mu * (1.f / 32.f);
    }
    for (int k = tid; k < 32; k += 256) {
        float mb = 0.f;
        for (int kk = 0; kk < 32; kk++) mb += f2b[kk];
        g_bh[k] = f2b[k] - mb * (1.f / 32.f);
    }
}

// ---------------------------------------------------------------------------
__global__ void __launch_bounds__(128) prep_kernel(const float* __restrict__ x)
{
    int n = blockIdx.x * 128 + threadIdx.x;
    int z = blockIdx.z;
    const float4* h4 = reinterpret_cast<const float4*>(x + ((size_t)z * NTOK + n) * NH);
    float4* o = g_ftr + (size_t)z * SLICE + n;
#pragma unroll
    for (int c = 0; c < 8; c++) o[(size_t)c * NTOK] = h4[c];
    int p = n & 4095;
    float4 lab;
    lab.x = (float)(p >> 6) * (1.f / 64.f);
    lab.y = (float)(p & 63) * (1.f / 64.f);
    lab.z = 0.f; lab.w = 0.f;
    o[(size_t)8 * NTOK] = lab;
}

// ---------------------------------------------------------------------------
__global__ void __launch_bounds__(128) step_kernel(
    int fin_slice, int fout_slice, float* __restrict__ outbase, int zmul,
    const float* __restrict__ lng, const float* __restrict__ lnb)
{
    __shared__ __align__(16) float sM[36][36];
    __shared__ __align__(16) float sCV[36][32];
    __shared__ __align__(16) float sF2[32][32];
    __shared__ __align__(16) float sKB[36];
    __shared__ float sQB[36], sCB2[32], sBH[32], sG[32], sBB[32];
    __shared__ float sCC;

    int tid = threadIdx.x;
    for (int idx = tid; idx < 36 * 36; idx += 128) sM[idx / 36][idx % 36] = g_M[idx];
    for (int idx = tid; idx < 36 * 32; idx += 128) sCV[idx / 32][idx % 32] = g_cv[idx / 32][idx % 32];
    for (int idx = tid; idx < 32 * 32; idx += 128) sF2[idx / 32][idx % 32] = g_f2h[idx / 32][idx % 32];
    if (tid < 36) { sKB[tid] = g_kb[tid]; sQB[tid] = g_qb[tid]; }
    if (tid < 32) {
        sCB2[tid] = g_cb2[tid]; sBH[tid] = g_bh[tid];
        sG[tid] = lng[tid];     sBB[tid] = lnb[tid];
    }
    if (tid == 0) sCC = g_cc[0];
    __syncthreads();

    int z = blockIdx.z;
    const float4* fin = g_ftr + (size_t)(fin_slice + z * zmul) * SLICE;
    float4* fout      = g_ftr + (size_t)(fout_slice + z * zmul) * SLICE;
    float* out        = outbase + (size_t)z * zmul * NTOK * NH;

    int n = blockIdx.x * 128 + tid;
    int p = n & 4095;
    int row = p >> 6, col = p & 63;
    int rs = row + (row == 0) - (row == 63);
    int cs = col + (col == 0) - (col == 63);
    int jb = (n >> 12) * 4096;

    int jt[9];
#pragma unroll
    for (int s = 0; s < 9; s++) {
        int dr = s / 3 - 1, dc = s % 3 - 1;
        jt[s] = jb + (rs + dr) * 64 + (cs + dc);
    }

    // a = M^T f4 + kb ; c4 = qb.f4 + cc   (score_s = a.f_s + c4, pre-scaled)
    float f4f[36];
#pragma unroll
    for (int c = 0; c < 9; c++) {
        float4 v = fin[(size_t)c * NTOK + jt[4]];
        f4f[4 * c + 0] = v.x; f4f[4 * c + 1] = v.y;
        f4f[4 * c + 2] = v.z; f4f[4 * c + 3] = v.w;
    }
    float c4 = sCC;
#pragma unroll
    for (int i = 0; i < 34; i++) c4 += f4f[i] * sQB[i];

    u64 a[18];
#pragma unroll
    for (int t = 0; t < 18; t++) a[t] = *reinterpret_cast<const u64*>(&sKB[2 * t]);
#pragma unroll
    for (int i = 0; i < 34; i++) {
        u64 fp = pack2(f4f[i], f4f[i]);
#pragma unroll
        for (int t = 0; t < 18; t++)
            a[t] = ffma2(fp, *reinterpret_cast<const u64*>(&sM[i][2 * t]), a[t]);
    }

    // online softmax over 9 neighbors accumulating fbar
    u64 fb[18];
#pragma unroll
    for (int t = 0; t < 18; t++) fb[t] = 0ull;
    float m = -1e30f, l = 0.f;

#pragma unroll
    for (int s = 0; s < 9; s++) {
        const float4* fp4 = fin + jt[s];
        u64 fs[18];
#pragma unroll
        for (int c = 0; c < 9; c++) {
            ulonglong2 v = *reinterpret_cast<const ulonglong2*>(&fp4[(size_t)c * NTOK]);
            fs[2 * c] = v.x; fs[2 * c + 1] = v.y;
        }
        u64 d0 = 0ull, d1 = 0ull;
#pragma unroll
        for (int t = 0; t < 9; t++) {
            d0 = ffma2(a[2 * t], fs[2 * t], d0);
            d1 = ffma2(a[2 * t + 1], fs[2 * t + 1], d1);
        }
        float x0, x1, x2, x3;
        unpack2(d0, x0, x1); unpack2(d1, x2, x3);
        float sc = (x0 + x1) + (x2 + x3) + c4;

        float m2 = fmaxf(m, sc);
        float cold = __expf(m - m2);
        float e = __expf(sc - m2);
        l = l * cold + e;
        u64 cp = pack2(cold, cold), ep = pack2(e, e);
#pragma unroll
        for (int t = 0; t < 18; t++)
            fb[t] = ffma2(ep, fs[t], fmul2(fb[t], cp));
        m = m2;
    }
    float rl = 1.f / l;
    u64 rlp = pack2(rl, rl);
    float fbf[36];
#pragma unroll
    for (int t = 0; t < 18; t++) {
        fb[t] = fmul2(fb[t], rlp);
        unpack2(fb[t], fbf[2 * t], fbf[2 * t + 1]);
    }

    // z = h_n + CV @ fbar + cb2
    u64 zacc[16];
#pragma unroll
    for (int t = 0; t < 16; t++) zacc[t] = *reinterpret_cast<const u64*>(&sCB2[2 * t]);
#pragma unroll
    for (int c = 0; c < 8; c++) {
        ulonglong2 hv = *reinterpret_cast<const ulonglong2*>(&fin[(size_t)c * NTOK + n]);
        zacc[2 * c]     = fadd2(zacc[2 * c], hv.x);
        zacc[2 * c + 1] = fadd2(zacc[2 * c + 1], hv.y);
    }
#pragma unroll
    for (int j = 0; j < 34; j++) {
        u64 fp = pack2(fbf[j], fbf[j]);
#pragma unroll
        for (int t = 0; t < 16; t++)
            zacc[t] = ffma2(fp, *reinterpret_cast<const u64*>(&sCV[j][2 * t]), zacc[t]);
    }
    float zf[32];
#pragma unroll
    for (int t = 0; t < 16; t++) unpack2(zacc[t], zf[2 * t], zf[2 * t + 1]);

    // v = F-hat @ z + b-hat (zero mean by construction)
    u64 vacc[16];
#pragma unroll
    for (int t = 0; t < 16; t++) vacc[t] = *reinterpret_cast<const u64*>(&sBH[2 * t]);
#pragma unroll
    for (int i = 0; i < 32; i++) {
        u64 fp = pack2(zf[i], zf[i]);
#pragma unroll
        for (int t = 0; t < 16; t++)
            vacc[t] = ffma2(fp, *reinterpret_cast<const u64*>(&sF2[i][2 * t]), vacc[t]);
    }
    float vf[32];
#pragma unroll
    for (int t = 0; t < 16; t++) unpack2(vacc[t], vf[2 * t], vf[2 * t + 1]);

    float var = 0.f;
#pragma unroll
    for (int k = 0; k < 32; k++) var += vf[k] * vf[k];
    float r = rsqrtf(var * (1.f / 32.f) + 1e-5f);

    float o[32];
#pragma unroll
    for (int k = 0; k < 32; k++) o[k] = vf[k] * r * sG[k] + sBB[k];

    float4* orow = reinterpret_cast<float4*>(out + (size_t)n * NH);
#pragma unroll
    for (int c = 0; c < 8; c++) {
        float4 y;
        y.x = o[4 * c + 0]; y.y = o[4 * c + 1];
        y.z = o[4 * c + 2]; y.w = o[4 * c + 3];
        orow[c] = y;
        fout[(size_t)c * NTOK + n] = y;
    }
    float4 lab;
    lab.x = (float)row * (1.f / 64.f);
    lab.y = (float)col * (1.f / 64.f);
    lab.z = 0.f; lab.w = 0.f;
    fout[(size_t)8 * NTOK + n] = lab;
}

// ---------------------------------------------------------------------------
extern "C" void kernel_launch(void* const* d_in, const int* in_sizes, int n_in,
                              void* d_out, int out_size)
{
    const float* x   = (const float*)d_in[0];
    const float* ipw = (const float*)d_in[1];
    const float* ipb = (const float*)d_in[2];
    const float* opw = (const float*)d_in[3];
    const float* opb = (const float*)d_in[4];
    const float* saw = (const float*)d_in[5];
    const float* sab = (const float*)d_in[6];
    const float* f2w = (const float*)d_in[7];
    const float* f2b = (const float*)d_in[8];
    const float* lng = (const float*)d_in[9];
    const float* lnb = (const float*)d_in[10];
    float* out = (float*)d_out;

    precomp_kernel<<<1, 256>>>(ipw, ipb, opw, opb, saw, sab, f2w, f2b);

    const int NB = NTOK / 128;

    prep_kernel<<<dim3(NB, 1, 10), 128>>>(x);

    // Observation: slices 0..9 -> 10..19, output rows 0..9
    step_kernel<<<dim3(NB, 1, 10), 128>>>(0, 10, out, 1, lng, lnb);

    // Prediction: 50 sequential steps; slice 19 seeds ping-pong 20/21
    for (int i = 0; i < 50; i++) {
        int fin = (i == 0) ? 19 : 20 + ((i - 1) & 1);
        int fot = 20 + (i & 1);
        float* o = out + (size_t)(10 + i) * NTOK * NH;
        step_kernel<<<dim3(NB, 1, 1), 128>>>(fin, fot, o, 0, lng, lnb);
    }
}